// round 2
// baseline (speedup 1.0000x reference)
#include <cuda_runtime.h>
#include <cstdint>
#include <cstddef>

// ---------------------------------------------------------------------------
// Pipeline:
//   inputs (4,3,512,512) f32
//   conv1 3->64 @512², BN1 (folded into conv2 input loader)
//   conv2 64->64 @512², BN2+ReLU -> skip_con (output 2)
//   Haar DWT -> (4,256,256,256)
//   conv3 256->64 @256², BN3+ReLU -> dwt_out (output 1)
//   d_out layout: [dwt_out 16,777,216 f32][skip_con 67,108,864 f32]
// ---------------------------------------------------------------------------

#define DWT_ELEMS  16777216ull           // 4*64*256*256
#define SKIP_ELEMS 67108864ull           // 4*64*512*512

// Scratch (allocation-free: device globals). bufA: x1 then dwt. bufB: x2.
__device__ float g_bufA[67108864];
__device__ float g_bufB[67108864];

// BN statistics + folded scale/shift, 3 stages x 64 channels
__device__ double g_sum[3][64];
__device__ double g_sq [3][64];
__device__ float  g_nsc[3][64];
__device__ float  g_nsh[3][64];

// ---------------------------------------------------------------------------
__global__ void zero_stats_kernel() {
    int i = threadIdx.x;
    if (i < 192) {
        ((double*)g_sum)[i] = 0.0;
        ((double*)g_sq )[i] = 0.0;
    }
}

// mean/var -> scale/shift.  scale = gamma*rsqrt(var+eps), shift = beta - mean*scale
__global__ void finalize_stats_kernel(int stage,
                                      const float* __restrict__ gamma,
                                      const float* __restrict__ beta,
                                      double inv_cnt) {
    int c = threadIdx.x;
    if (c < 64) {
        double m   = g_sum[stage][c] * inv_cnt;
        double var = g_sq [stage][c] * inv_cnt - m * m;
        double sc  = (double)gamma[c] / sqrt(var + 1e-5);
        g_nsc[stage][c] = (float)sc;
        g_nsh[stage][c] = (float)((double)beta[c] - m * sc);
    }
}

// ---------------------------------------------------------------------------
// Tiled direct 3x3 SAME conv, OC=64 fixed, C/H/W runtime.
// Block: 512 threads. Tile: 64 oc x 8 rows x 32 cols.
// Thread: col = tid&31, group g = tid>>5 (16 groups x 4 oc), 32 accumulators.
// Optional per-input-channel normalization (fused BN of previous stage):
//   value = in*nsc + nsh applied only to in-bounds loads (padding stays 0,
//   matching pad-after-BN semantics of the reference).
// Epilogue: write outputs + per-channel sum/sumsq (warp reduce + atomicAdd).
// ---------------------------------------------------------------------------
template<bool NORM>
__global__ __launch_bounds__(512)
void conv3x3_kernel(const float* __restrict__ in,
                    const float* __restrict__ wgt,    // [64][C][3][3]
                    const float* __restrict__ bias,   // [64]
                    float* __restrict__ out,          // [N][64][H][W]
                    int C, int H, int W,
                    int nstage, int ostage)
{
    __shared__ float sIn[10 * 34];
    __shared__ float sW [64 * 9];

    const int tid  = threadIdx.x;
    const int col  = tid & 31;
    const int g    = tid >> 5;       // 0..15
    const int oc0  = g * 4;
    const int col0 = blockIdx.x * 32;
    const int row0 = blockIdx.y * 8;
    const int n    = blockIdx.z;

    float acc[4][8];
    #pragma unroll
    for (int ko = 0; ko < 4; ko++) {
        float b = bias[oc0 + ko];
        #pragma unroll
        for (int rr = 0; rr < 8; rr++) acc[ko][rr] = b;
    }

    for (int c = 0; c < C; c++) {
        // ---- load 10x34 input patch (zero padded) ----
        if (tid < 340) {
            int r  = tid / 34, cc = tid % 34;
            int gr = row0 - 1 + r;
            int gc = col0 - 1 + cc;
            float v = 0.0f;
            if (gr >= 0 && gr < H && gc >= 0 && gc < W) {
                v = in[((size_t)(n * C + c) * H + gr) * W + gc];
                if (NORM) v = fmaf(v, g_nsc[nstage][c], g_nsh[nstage][c]);
            }
            sIn[tid] = v;
        }
        // ---- load 64x9 weights for this input channel ----
        {
            int idx = tid;
            if (idx < 576) sW[idx] = wgt[((size_t)(idx / 9) * C + c) * 9 + (idx % 9)];
            idx += 512;
            if (idx < 576) sW[idx] = wgt[((size_t)(idx / 9) * C + c) * 9 + (idx % 9)];
        }
        __syncthreads();

        // ---- per-thread input strip: 10 rows x 3 cols ----
        float v[10][3];
        #pragma unroll
        for (int r = 0; r < 10; r++)
            #pragma unroll
            for (int dj = 0; dj < 3; dj++)
                v[r][dj] = sIn[r * 34 + col + dj];

        #pragma unroll
        for (int ko = 0; ko < 4; ko++) {
            float w[9];
            #pragma unroll
            for (int j = 0; j < 9; j++) w[j] = sW[(oc0 + ko) * 9 + j];
            #pragma unroll
            for (int rr = 0; rr < 8; rr++) {
                float s = acc[ko][rr];
                #pragma unroll
                for (int di = 0; di < 3; di++)
                    #pragma unroll
                    for (int dj = 0; dj < 3; dj++)
                        s = fmaf(w[di * 3 + dj], v[rr + di][dj], s);
                acc[ko][rr] = s;
            }
        }
        __syncthreads();
    }

    // ---- epilogue: store + BN statistics ----
    #pragma unroll
    for (int ko = 0; ko < 4; ko++) {
        float s = 0.0f, q = 0.0f;
        #pragma unroll
        for (int rr = 0; rr < 8; rr++) {
            float x = acc[ko][rr];
            out[((size_t)(n * 64 + oc0 + ko) * H + row0 + rr) * W + col0 + col] = x;
            s += x;
            q = fmaf(x, x, q);
        }
        #pragma unroll
        for (int off = 16; off; off >>= 1) {
            s += __shfl_down_sync(0xffffffffu, s, off);
            q += __shfl_down_sync(0xffffffffu, q, off);
        }
        if (col == 0) {
            atomicAdd(&g_sum[ostage][oc0 + ko], (double)s);
            atomicAdd(&g_sq [ostage][oc0 + ko], (double)q);
        }
    }
}

// ---------------------------------------------------------------------------
// Fused: skip = relu(BN2(x2)) AND Haar DWT of skip in one pass.
// Thread i owns one 2x2 block of skip == one spatial position of each subband.
//   x2   : (4,64,512,512)  raw conv2 output
//   skip : (4,64,512,512)  output 2
//   dwt  : (4,256,256,256) channels ordered [cA|cH|cV|cD]
// ---------------------------------------------------------------------------
__global__ void bnrelu_dwt_kernel(const float* __restrict__ x2,
                                  float* __restrict__ skip,
                                  float* __restrict__ dwt) {
    size_t i = (size_t)blockIdx.x * blockDim.x + threadIdx.x;
    if (i >= DWT_ELEMS) return;
    int x = (int)(i & 255);
    int y = (int)((i >> 8) & 255);
    int c = (int)((i >> 16) & 63);
    int n = (int)(i >> 22);

    const float sc = g_nsc[1][c];
    const float sh = g_nsh[1][c];

    const size_t base = ((size_t)(n * 64 + c) * 512 + 2 * y) * 512 + 2 * x;
    float2 r0 = *(const float2*)(x2 + base);
    float2 r1 = *(const float2*)(x2 + base + 512);

    float s00 = fmaxf(fmaf(r0.x, sc, sh), 0.0f);
    float s01 = fmaxf(fmaf(r0.y, sc, sh), 0.0f);
    float s10 = fmaxf(fmaf(r1.x, sc, sh), 0.0f);
    float s11 = fmaxf(fmaf(r1.y, sc, sh), 0.0f);

    *(float2*)(skip + base)       = make_float2(s00, s01);
    *(float2*)(skip + base + 512) = make_float2(s10, s11);

    size_t ob = ((size_t)(n * 256 + c)) * 65536 + (size_t)y * 256 + x;
    dwt[ob                 ] = 0.5f * (s00 + s01 + s10 + s11);  // cA
    dwt[ob +  64ull * 65536] = 0.5f * (s00 + s01 - s10 - s11);  // cH
    dwt[ob + 128ull * 65536] = 0.5f * (s00 - s01 + s10 - s11);  // cV
    dwt[ob + 192ull * 65536] = 0.5f * (s00 - s01 - s10 + s11);  // cD
}

// ---------------------------------------------------------------------------
// Final dwt_out = relu(BN3(y3)) in place, float4-vectorized.
// (4,64,256,256): channel = (elem_idx >> 16) & 63; 65536 % 4 == 0 so all four
// lanes of a float4 share one channel.
// ---------------------------------------------------------------------------
__global__ void bnrelu4_kernel(float* __restrict__ buf) {
    size_t i4 = (size_t)blockIdx.x * blockDim.x + threadIdx.x;   // float4 index
    if (i4 >= (DWT_ELEMS >> 2)) return;
    int c = (int)((i4 >> 14) & 63);                              // (i4*4)>>16
    const float sc = g_nsc[2][c];
    const float sh = g_nsh[2][c];
    float4 v = ((float4*)buf)[i4];
    v.x = fmaxf(fmaf(v.x, sc, sh), 0.0f);
    v.y = fmaxf(fmaf(v.y, sc, sh), 0.0f);
    v.z = fmaxf(fmaf(v.z, sc, sh), 0.0f);
    v.w = fmaxf(fmaf(v.w, sc, sh), 0.0f);
    ((float4*)buf)[i4] = v;
}

// ---------------------------------------------------------------------------
extern "C" void kernel_launch(void* const* d_in, const int* in_sizes, int n_in,
                              void* d_out, int out_size) {
    const float* x   = (const float*)d_in[0];
    const float* w1  = (const float*)d_in[1];
    const float* b1  = (const float*)d_in[2];
    const float* g1  = (const float*)d_in[3];
    const float* be1 = (const float*)d_in[4];
    const float* w2  = (const float*)d_in[5];
    const float* b2  = (const float*)d_in[6];
    const float* g2  = (const float*)d_in[7];
    const float* be2 = (const float*)d_in[8];
    const float* w3  = (const float*)d_in[9];
    const float* b3  = (const float*)d_in[10];
    const float* g3  = (const float*)d_in[11];
    const float* be3 = (const float*)d_in[12];

    float* out      = (float*)d_out;
    float* dwt_out  = out;                    // 16,777,216 floats
    float* skip_con = out + DWT_ELEMS;        // 67,108,864 floats

    float *bufA, *bufB;
    cudaGetSymbolAddress((void**)&bufA, g_bufA);
    cudaGetSymbolAddress((void**)&bufB, g_bufB);

    const double inv_cnt_hi = 1.0 / (4.0 * 512.0 * 512.0);
    const double inv_cnt_lo = 1.0 / (4.0 * 256.0 * 256.0);

    // 0) zero BN accumulators (graph-replay safe)
    zero_stats_kernel<<<1, 192>>>();

    // 1) conv1: input -> bufA (x1), stats stage 0
    conv3x3_kernel<false><<<dim3(16, 64, 4), 512>>>(x, w1, b1, bufA, 3, 512, 512, 0, 0);
    finalize_stats_kernel<<<1, 64>>>(0, g1, be1, inv_cnt_hi);

    // 2) conv2 with fused BN1 on input: bufA -> bufB (x2), stats stage 1
    conv3x3_kernel<true><<<dim3(16, 64, 4), 512>>>(bufA, w2, b2, bufB, 64, 512, 512, 0, 1);
    finalize_stats_kernel<<<1, 64>>>(1, g2, be2, inv_cnt_hi);

    // 3) fused: skip_con = relu(BN2(x2)); dwt(skip_con) -> bufA (4,256,256,256)
    bnrelu_dwt_kernel<<<65536, 256>>>(bufB, skip_con, bufA);

    // 4) conv3: dwt -> dwt_out region (raw, pre-BN), stats stage 2
    conv3x3_kernel<false><<<dim3(8, 32, 4), 512>>>(bufA, w3, b3, dwt_out, 256, 256, 256, 0, 2);
    finalize_stats_kernel<<<1, 64>>>(2, g3, be3, inv_cnt_lo);

    // 5) dwt_out = relu(BN3(y3)) in place (float4)
    bnrelu4_kernel<<<16384, 256>>>(dwt_out);
}

// round 3
// speedup vs baseline: 1.1302x; 1.1302x over previous
#include <cuda_runtime.h>
#include <cstdint>
#include <cstddef>

// ---------------------------------------------------------------------------
// Pipeline:
//   inputs (4,3,512,512) f32
//   conv1 3->64 @512², BN1 (folded into conv2 input loader)
//   conv2 64->64 @512², BN2+ReLU -> skip_con (output 2)
//   Haar DWT -> (4,256,256,256)
//   conv3 256->64 @256², BN3+ReLU -> dwt_out (output 1)
//   d_out layout: [dwt_out 16,777,216 f32][skip_con 67,108,864 f32]
// ---------------------------------------------------------------------------

#define DWT_ELEMS  16777216ull           // 4*64*256*256
#define SKIP_ELEMS 67108864ull           // 4*64*512*512

// Scratch (allocation-free: device globals). bufA: x1 then dwt. bufB: x2.
__device__ float g_bufA[67108864];
__device__ float g_bufB[67108864];
__device__ float g_wT[256 * 576];        // transposed weights [c][oc*9+j], reused per stage

// BN statistics + folded scale/shift, 3 stages x 64 channels
__device__ double g_sum[3][64];
__device__ double g_sq [3][64];
__device__ float  g_nsc[3][64];
__device__ float  g_nsh[3][64];

// ---------------------------------------------------------------------------
__global__ void zero_stats_kernel() {
    int i = threadIdx.x;
    if (i < 192) {
        ((double*)g_sum)[i] = 0.0;
        ((double*)g_sq )[i] = 0.0;
    }
}

// mean/var -> scale/shift.  scale = gamma*rsqrt(var+eps), shift = beta - mean*scale
__global__ void finalize_stats_kernel(int stage,
                                      const float* __restrict__ gamma,
                                      const float* __restrict__ beta,
                                      double inv_cnt) {
    int c = threadIdx.x;
    if (c < 64) {
        double m   = g_sum[stage][c] * inv_cnt;
        double var = g_sq [stage][c] * inv_cnt - m * m;
        double sc  = (double)gamma[c] / sqrt(var + 1e-5);
        g_nsc[stage][c] = (float)sc;
        g_nsh[stage][c] = (float)((double)beta[c] - m * sc);
    }
}

// ---------------------------------------------------------------------------
// Weight reformat: w[oc][c][3][3] -> wT[c][oc*9+j]  (coalesced per-channel slab)
// ---------------------------------------------------------------------------
__global__ void transpose_w_kernel(const float* __restrict__ w,
                                   float* __restrict__ wT, int C) {
    int i = blockIdx.x * blockDim.x + threadIdx.x;
    if (i < C * 576) {
        int c = i / 576, r = i % 576;            // r = oc*9 + j
        wT[i] = w[((size_t)(r / 9) * C + c) * 9 + (r % 9)];
    }
}

// ---------------------------------------------------------------------------
// Tiled direct 3x3 SAME conv, OC=64 fixed, C/H/W runtime, DOUBLE-BUFFERED.
// Block: 512 threads. Tile: 64 oc x 8 rows x 32 cols.
// Thread: col = tid&31, group g = tid>>5 (16 groups x 4 oc), 32 accumulators.
// Per channel: load c+1 (global->regs) BEFORE computing c (hides latency),
// then regs->smem ping-pong buffer, ONE barrier per channel.
// NORM: fold previous stage's BN into the input loader (padding stays 0,
// matching pad-after-BN semantics of the reference).
// Epilogue: write outputs + per-channel sum/sumsq (warp reduce + atomicAdd).
// ---------------------------------------------------------------------------
template<bool NORM>
__global__ __launch_bounds__(512)
void conv3x3_kernel(const float* __restrict__ in,
                    const float* __restrict__ wT,     // [C][576]
                    const float* __restrict__ bias,   // [64]
                    float* __restrict__ out,          // [N][64][H][W]
                    int C, int H, int W,
                    int nstage, int ostage)
{
    __shared__ float sIn[2][10 * 34];
    __shared__ float sW [2][576];

    const int tid  = threadIdx.x;
    const int col  = tid & 31;
    const int g    = tid >> 5;       // 0..15
    const int oc0  = g * 4;
    const int col0 = blockIdx.x * 32;
    const int row0 = blockIdx.y * 8;
    const int n    = blockIdx.z;

    // static per-thread load geometry
    const int  lr   = tid / 34, lc = tid % 34;           // patch coords (tid<340)
    const int  gr   = row0 - 1 + lr;
    const int  gc   = col0 - 1 + lc;
    const bool ldin = (tid < 340) && gr >= 0 && gr < H && gc >= 0 && gc < W;
    const bool pat  = (tid < 340);
    const size_t in_off = ((size_t)n * C * H + (size_t)gr) * W + gc; // +c*H*W per chan
    const bool ldw2 = (tid < 64);                         // second weight element

    float acc[4][8];
    #pragma unroll
    for (int ko = 0; ko < 4; ko++) {
        float b = bias[oc0 + ko];
        #pragma unroll
        for (int rr = 0; rr < 8; rr++) acc[ko][rr] = b;
    }

    // ---- prologue: stage channel 0 ----
    {
        float v = 0.0f;
        if (ldin) {
            v = in[in_off];
            if (NORM) v = fmaf(v, g_nsc[nstage][0], g_nsh[nstage][0]);
        }
        if (pat) sIn[0][tid] = v;
        sW[0][tid] = (tid < 576) ? wT[tid] : 0.0f;
        if (ldw2) sW[0][tid + 512] = wT[tid + 512];
    }
    __syncthreads();

    int b = 0;
    for (int c = 0; c < C; c++) {
        // ---- issue loads for channel c+1 (hidden behind compute) ----
        float nv = 0.0f, nw0 = 0.0f, nw1 = 0.0f;
        const bool more = (c + 1 < C);
        if (more) {
            if (ldin) {
                nv = in[in_off + (size_t)(c + 1) * H * W];
                if (NORM) nv = fmaf(nv, g_nsc[nstage][c + 1], g_nsh[nstage][c + 1]);
            }
            const float* wrow = wT + (size_t)(c + 1) * 576;
            if (tid < 576) nw0 = wrow[tid];
            if (ldw2)      nw1 = wrow[tid + 512];
        }

        // ---- per-thread input strip: 10 rows x 3 cols ----
        float v[10][3];
        #pragma unroll
        for (int r = 0; r < 10; r++)
            #pragma unroll
            for (int dj = 0; dj < 3; dj++)
                v[r][dj] = sIn[b][r * 34 + col + dj];

        #pragma unroll
        for (int ko = 0; ko < 4; ko++) {
            float w[9];
            #pragma unroll
            for (int j = 0; j < 9; j++) w[j] = sW[b][(oc0 + ko) * 9 + j];
            #pragma unroll
            for (int rr = 0; rr < 8; rr++) {
                float s = acc[ko][rr];
                #pragma unroll
                for (int di = 0; di < 3; di++)
                    #pragma unroll
                    for (int dj = 0; dj < 3; dj++)
                        s = fmaf(w[di * 3 + dj], v[rr + di][dj], s);
                acc[ko][rr] = s;
            }
        }

        // ---- stage channel c+1 into the other buffer ----
        if (more) {
            if (pat) sIn[b ^ 1][tid] = nv;
            if (tid < 576) sW[b ^ 1][tid] = nw0;
            if (ldw2)      sW[b ^ 1][tid + 512] = nw1;
        }
        __syncthreads();
        b ^= 1;
    }

    // ---- epilogue: store + BN statistics ----
    #pragma unroll
    for (int ko = 0; ko < 4; ko++) {
        float s = 0.0f, q = 0.0f;
        #pragma unroll
        for (int rr = 0; rr < 8; rr++) {
            float x = acc[ko][rr];
            out[((size_t)(n * 64 + oc0 + ko) * H + row0 + rr) * W + col0 + col] = x;
            s += x;
            q = fmaf(x, x, q);
        }
        #pragma unroll
        for (int off = 16; off; off >>= 1) {
            s += __shfl_down_sync(0xffffffffu, s, off);
            q += __shfl_down_sync(0xffffffffu, q, off);
        }
        if (col == 0) {
            atomicAdd(&g_sum[ostage][oc0 + ko], (double)s);
            atomicAdd(&g_sq [ostage][oc0 + ko], (double)q);
        }
    }
}

// ---------------------------------------------------------------------------
// Fused: skip = relu(BN2(x2)) AND Haar DWT of skip in one pass.
// Thread i owns one 2x2 block of skip == one spatial position of each subband.
// ---------------------------------------------------------------------------
__global__ void bnrelu_dwt_kernel(const float* __restrict__ x2,
                                  float* __restrict__ skip,
                                  float* __restrict__ dwt) {
    size_t i = (size_t)blockIdx.x * blockDim.x + threadIdx.x;
    if (i >= DWT_ELEMS) return;
    int x = (int)(i & 255);
    int y = (int)((i >> 8) & 255);
    int c = (int)((i >> 16) & 63);
    int n = (int)(i >> 22);

    const float sc = g_nsc[1][c];
    const float sh = g_nsh[1][c];

    const size_t base = ((size_t)(n * 64 + c) * 512 + 2 * y) * 512 + 2 * x;
    float2 r0 = *(const float2*)(x2 + base);
    float2 r1 = *(const float2*)(x2 + base + 512);

    float s00 = fmaxf(fmaf(r0.x, sc, sh), 0.0f);
    float s01 = fmaxf(fmaf(r0.y, sc, sh), 0.0f);
    float s10 = fmaxf(fmaf(r1.x, sc, sh), 0.0f);
    float s11 = fmaxf(fmaf(r1.y, sc, sh), 0.0f);

    *(float2*)(skip + base)       = make_float2(s00, s01);
    *(float2*)(skip + base + 512) = make_float2(s10, s11);

    size_t ob = ((size_t)(n * 256 + c)) * 65536 + (size_t)y * 256 + x;
    dwt[ob                 ] = 0.5f * (s00 + s01 + s10 + s11);  // cA
    dwt[ob +  64ull * 65536] = 0.5f * (s00 + s01 - s10 - s11);  // cH
    dwt[ob + 128ull * 65536] = 0.5f * (s00 - s01 + s10 - s11);  // cV
    dwt[ob + 192ull * 65536] = 0.5f * (s00 - s01 - s10 + s11);  // cD
}

// ---------------------------------------------------------------------------
// Final dwt_out = relu(BN3(y3)) in place, float4-vectorized.
// ---------------------------------------------------------------------------
__global__ void bnrelu4_kernel(float* __restrict__ buf) {
    size_t i4 = (size_t)blockIdx.x * blockDim.x + threadIdx.x;   // float4 index
    if (i4 >= (DWT_ELEMS >> 2)) return;
    int c = (int)((i4 >> 14) & 63);                              // (i4*4)>>16
    const float sc = g_nsc[2][c];
    const float sh = g_nsh[2][c];
    float4 v = ((float4*)buf)[i4];
    v.x = fmaxf(fmaf(v.x, sc, sh), 0.0f);
    v.y = fmaxf(fmaf(v.y, sc, sh), 0.0f);
    v.z = fmaxf(fmaf(v.z, sc, sh), 0.0f);
    v.w = fmaxf(fmaf(v.w, sc, sh), 0.0f);
    ((float4*)buf)[i4] = v;
}

// ---------------------------------------------------------------------------
extern "C" void kernel_launch(void* const* d_in, const int* in_sizes, int n_in,
                              void* d_out, int out_size) {
    const float* x   = (const float*)d_in[0];
    const float* w1  = (const float*)d_in[1];
    const float* b1  = (const float*)d_in[2];
    const float* g1  = (const float*)d_in[3];
    const float* be1 = (const float*)d_in[4];
    const float* w2  = (const float*)d_in[5];
    const float* b2  = (const float*)d_in[6];
    const float* g2  = (const float*)d_in[7];
    const float* be2 = (const float*)d_in[8];
    const float* w3  = (const float*)d_in[9];
    const float* b3  = (const float*)d_in[10];
    const float* g3  = (const float*)d_in[11];
    const float* be3 = (const float*)d_in[12];

    float* out      = (float*)d_out;
    float* dwt_out  = out;                    // 16,777,216 floats
    float* skip_con = out + DWT_ELEMS;        // 67,108,864 floats

    float *bufA, *bufB, *wT;
    cudaGetSymbolAddress((void**)&bufA, g_bufA);
    cudaGetSymbolAddress((void**)&bufB, g_bufB);
    cudaGetSymbolAddress((void**)&wT,   g_wT);

    const double inv_cnt_hi = 1.0 / (4.0 * 512.0 * 512.0);
    const double inv_cnt_lo = 1.0 / (4.0 * 256.0 * 256.0);

    // 0) zero BN accumulators (graph-replay safe)
    zero_stats_kernel<<<1, 192>>>();

    // 1) conv1: input -> bufA (x1), stats stage 0
    transpose_w_kernel<<<(3 * 576 + 255) / 256, 256>>>(w1, wT, 3);
    conv3x3_kernel<false><<<dim3(16, 64, 4), 512>>>(x, wT, b1, bufA, 3, 512, 512, 0, 0);
    finalize_stats_kernel<<<1, 64>>>(0, g1, be1, inv_cnt_hi);

    // 2) conv2 with fused BN1 on input: bufA -> bufB (x2), stats stage 1
    transpose_w_kernel<<<(64 * 576 + 255) / 256, 256>>>(w2, wT, 64);
    conv3x3_kernel<true><<<dim3(16, 64, 4), 512>>>(bufA, wT, b2, bufB, 64, 512, 512, 0, 1);
    finalize_stats_kernel<<<1, 64>>>(1, g2, be2, inv_cnt_hi);

    // 3) fused: skip_con = relu(BN2(x2)); dwt(skip_con) -> bufA (4,256,256,256)
    bnrelu_dwt_kernel<<<65536, 256>>>(bufB, skip_con, bufA);

    // 4) conv3: dwt -> dwt_out region (raw, pre-BN), stats stage 2
    transpose_w_kernel<<<(256 * 576 + 255) / 256, 256>>>(w3, wT, 256);
    conv3x3_kernel<false><<<dim3(8, 32, 4), 512>>>(bufA, wT, b3, dwt_out, 256, 256, 256, 0, 2);
    finalize_stats_kernel<<<1, 64>>>(2, g3, be3, inv_cnt_lo);

    // 5) dwt_out = relu(BN3(y3)) in place (float4)
    bnrelu4_kernel<<<16384, 256>>>(dwt_out);
}

// round 5
// speedup vs baseline: 2.9723x; 2.6300x over previous
#include <cuda_runtime.h>
#include <cuda_bf16.h>
#include <cstdint>
#include <cstddef>

// ---------------------------------------------------------------------------
// Pipeline:
//   inputs (4,3,512,512) f32
//   conv1 3->64 @512² (FFMA), BN1 folded into conv2 loader
//   conv2 64->64 @512²  -- mma.sync bf16 3-term implicit GEMM (tensor pipe)
//   BN2+ReLU -> skip_con (output 2), fused with Haar DWT
//   conv3 256->64 @256² -- mma.sync bf16 3-term implicit GEMM
//   BN3+ReLU -> dwt_out (output 1)
//   d_out layout: [dwt_out 16,777,216 f32][skip_con 67,108,864 f32]
// NOTE: harness compiles PTX at compute_100 => tcgen05 unavailable; using
// sm_80-class mma.sync/ldmatrix which are legal at this PTX target.
// ---------------------------------------------------------------------------

#define DWT_ELEMS  16777216ull
#define SKIP_ELEMS 67108864ull

__device__ float g_bufA[67108864];
__device__ float g_bufB[67108864];
__device__ float g_wT[256 * 576];              // conv1 FFMA weights [c][oc*9+j]
__device__ __nv_bfloat16 g_wB[331776];         // mma weights [tt][term][oc][72]

__device__ double g_sum[3][64];
__device__ double g_sq [3][64];
__device__ float  g_nsc[3][64];
__device__ float  g_nsh[3][64];

// ============================ helpers ======================================
__device__ __forceinline__ uint32_t smem_u32(const void* p) {
    uint32_t a;
    asm("{ .reg .u64 t; cvta.to.shared.u64 t, %1; cvt.u32.u64 %0, t; }" : "=r"(a) : "l"(p));
    return a;
}
__device__ __forceinline__ void ldmatrix4(uint32_t* r, uint32_t addr) {
    asm volatile("ldmatrix.sync.aligned.m8n8.x4.shared.b16 {%0,%1,%2,%3}, [%4];"
                 : "=r"(r[0]), "=r"(r[1]), "=r"(r[2]), "=r"(r[3]) : "r"(addr));
}
__device__ __forceinline__ void mma_bf16(float* c, const uint32_t* a, const uint32_t* b) {
    asm volatile(
        "mma.sync.aligned.m16n8k16.row.col.f32.bf16.bf16.f32 "
        "{%0,%1,%2,%3}, {%4,%5,%6,%7}, {%8,%9}, {%0,%1,%2,%3};"
        : "+f"(c[0]), "+f"(c[1]), "+f"(c[2]), "+f"(c[3])
        : "r"(a[0]), "r"(a[1]), "r"(a[2]), "r"(a[3]), "r"(b[0]), "r"(b[1]));
}

// ============================ small kernels ================================
__global__ void zero_stats_kernel() {
    int i = threadIdx.x;
    if (i < 192) { ((double*)g_sum)[i] = 0.0; ((double*)g_sq)[i] = 0.0; }
}

__global__ void finalize_stats_kernel(int stage, const float* __restrict__ gamma,
                                      const float* __restrict__ beta, double inv_cnt) {
    int c = threadIdx.x;
    if (c < 64) {
        double m   = g_sum[stage][c] * inv_cnt;
        double var = g_sq [stage][c] * inv_cnt - m * m;
        double sc  = (double)gamma[c] / sqrt(var + 1e-5);
        g_nsc[stage][c] = (float)sc;
        g_nsh[stage][c] = (float)((double)beta[c] - m * sc);
    }
}

// Deterministic per-channel BN stats -> scale/shift. grid=64, block=1024.
__global__ void stats2_kernel(const float* __restrict__ buf, int stage, int HW,
                              const float* __restrict__ gamma, const float* __restrict__ beta) {
    __shared__ double wS[32], wQ[32];
    int c = blockIdx.x, tid = threadIdx.x;
    double s = 0.0, q = 0.0;
    for (int n = 0; n < 4; n++) {
        const float4* p = (const float4*)(buf + ((size_t)(n * 64 + c)) * HW);
        int n4 = HW >> 2;
        for (int i = tid; i < n4; i += 1024) {
            float4 v = p[i];
            s += (double)v.x + (double)v.y + (double)v.z + (double)v.w;
            q += (double)v.x * v.x + (double)v.y * v.y + (double)v.z * v.z + (double)v.w * v.w;
        }
    }
    for (int o = 16; o; o >>= 1) {
        s += __shfl_down_sync(0xffffffffu, s, o);
        q += __shfl_down_sync(0xffffffffu, q, o);
    }
    if ((tid & 31) == 0) { wS[tid >> 5] = s; wQ[tid >> 5] = q; }
    __syncthreads();
    if (tid < 32) {
        s = wS[tid]; q = wQ[tid];
        for (int o = 16; o; o >>= 1) {
            s += __shfl_down_sync(0xffffffffu, s, o);
            q += __shfl_down_sync(0xffffffffu, q, o);
        }
        if (tid == 0) {
            double inv = 1.0 / (4.0 * (double)HW);
            double m = s * inv, var = q * inv - m * m;
            double sc = (double)gamma[c] / sqrt(var + 1e-5);
            g_nsc[stage][c] = (float)sc;
            g_nsh[stage][c] = (float)((double)beta[c] - m * sc);
        }
    }
}

// conv1 FFMA weight reformat: w[oc][c][3][3] -> wT[c][oc*9+j]
__global__ void transpose_w_kernel(const float* __restrict__ w, float* __restrict__ wT, int C) {
    int i = blockIdx.x * blockDim.x + threadIdx.x;
    if (i < C * 576) {
        int c = i / 576, r = i % 576;
        wT[i] = w[((size_t)(r / 9) * C + c) * 9 + (r % 9)];
    }
}

// mma weight prep: w[oc][C][9] -> wB[tt= slab*9+tap][term hi/lo][oc][72ch] bf16
__global__ void prep_wmma_kernel(const float* __restrict__ w,
                                 __nv_bfloat16* __restrict__ wB, int C) {
    int i = blockIdx.x * blockDim.x + threadIdx.x;
    int nSlabs = C >> 6;
    int total = nSlabs * 9 * 2 * 64 * 72;
    if (i >= total) return;
    int ch   = i % 72;
    int oc   = (i / 72) % 64;
    int term = (i / (72 * 64)) % 2;
    int tt   = i / (72 * 64 * 2);
    int slab = tt / 9, tap = tt % 9;
    float v = 0.0f;
    if (ch < 64) v = w[((size_t)oc * C + slab * 64 + ch) * 9 + tap];
    __nv_bfloat16 h = __float2bfloat16(v);
    wB[i] = (term == 0) ? h : __float2bfloat16(v - __bfloat162float(h));
}

// ================= conv1: direct FFMA 3x3 (known-good, C=3) =================
template<bool NORM>
__global__ __launch_bounds__(512)
void conv3x3_kernel(const float* __restrict__ in, const float* __restrict__ wT,
                    const float* __restrict__ bias, float* __restrict__ out,
                    int C, int H, int W, int nstage, int ostage)
{
    __shared__ float sIn[2][10 * 34];
    __shared__ float sW [2][576];
    const int tid = threadIdx.x, col = tid & 31, g = tid >> 5, oc0 = g * 4;
    const int col0 = blockIdx.x * 32, row0 = blockIdx.y * 8, n = blockIdx.z;
    const int lr = tid / 34, lc = tid % 34;
    const int gr = row0 - 1 + lr, gc = col0 - 1 + lc;
    const bool ldin = (tid < 340) && gr >= 0 && gr < H && gc >= 0 && gc < W;
    const bool pat = (tid < 340);
    const size_t in_off = ((size_t)n * C * H + (size_t)gr) * W + gc;
    const bool ldw2 = (tid < 64);

    float acc[4][8];
    #pragma unroll
    for (int ko = 0; ko < 4; ko++) {
        float b = bias[oc0 + ko];
        #pragma unroll
        for (int rr = 0; rr < 8; rr++) acc[ko][rr] = b;
    }
    {
        float v = 0.0f;
        if (ldin) { v = in[in_off]; if (NORM) v = fmaf(v, g_nsc[nstage][0], g_nsh[nstage][0]); }
        if (pat) sIn[0][tid] = v;
        sW[0][tid] = (tid < 576) ? wT[tid] : 0.0f;
        if (ldw2) sW[0][tid + 512] = wT[tid + 512];
    }
    __syncthreads();
    int b = 0;
    for (int c = 0; c < C; c++) {
        float nv = 0.0f, nw0 = 0.0f, nw1 = 0.0f;
        const bool more = (c + 1 < C);
        if (more) {
            if (ldin) {
                nv = in[in_off + (size_t)(c + 1) * H * W];
                if (NORM) nv = fmaf(nv, g_nsc[nstage][c + 1], g_nsh[nstage][c + 1]);
            }
            const float* wrow = wT + (size_t)(c + 1) * 576;
            if (tid < 576) nw0 = wrow[tid];
            if (ldw2)      nw1 = wrow[tid + 512];
        }
        float v[10][3];
        #pragma unroll
        for (int r = 0; r < 10; r++)
            #pragma unroll
            for (int dj = 0; dj < 3; dj++) v[r][dj] = sIn[b][r * 34 + col + dj];
        #pragma unroll
        for (int ko = 0; ko < 4; ko++) {
            float w[9];
            #pragma unroll
            for (int j = 0; j < 9; j++) w[j] = sW[b][(oc0 + ko) * 9 + j];
            #pragma unroll
            for (int rr = 0; rr < 8; rr++) {
                float s = acc[ko][rr];
                #pragma unroll
                for (int di = 0; di < 3; di++)
                    #pragma unroll
                    for (int dj = 0; dj < 3; dj++)
                        s = fmaf(w[di * 3 + dj], v[rr + di][dj], s);
                acc[ko][rr] = s;
            }
        }
        if (more) {
            if (pat) sIn[b ^ 1][tid] = nv;
            if (tid < 576) sW[b ^ 1][tid] = nw0;
            if (ldw2)      sW[b ^ 1][tid + 512] = nw1;
        }
        __syncthreads();
        b ^= 1;
    }
    #pragma unroll
    for (int ko = 0; ko < 4; ko++) {
        float s = 0.0f, q = 0.0f;
        #pragma unroll
        for (int rr = 0; rr < 8; rr++) {
            float x = acc[ko][rr];
            out[((size_t)(n * 64 + oc0 + ko) * H + row0 + rr) * W + col0 + col] = x;
            s += x; q = fmaf(x, x, q);
        }
        #pragma unroll
        for (int off = 16; off; off >>= 1) {
            s += __shfl_down_sync(0xffffffffu, s, off);
            q += __shfl_down_sync(0xffffffffu, q, off);
        }
        if (col == 0) {
            atomicAdd(&g_sum[ostage][oc0 + ko], (double)s);
            atomicAdd(&g_sq [ostage][oc0 + ko], (double)q);
        }
    }
}

// ============ conv2/conv3: mma.sync bf16 implicit GEMM =====================
// Block 256 thr (8 warps, 4m x 2n). Output tile 128 pixels (8x16) x 64 oc.
// Warp tile 32m x 32n. K = channels; taps via ldmatrix address shift into a
// shared 10x18 patch (bf16 hi/lo, 72-ch pad = 144B rows, conflict-free).
// 3-term split: Ah*Bh + Ah*Bl + Al*Bh.
// SMEM: [0]      A_hi patch 180x72 bf16 (25,920)   } reused as f32 C staging
//       [25920]  A_lo patch              (25,920)  }
//       [51840]  B double buffer: 2 x [term][64][72] bf16 (2 x 18,432)
//       [88704]  bias f32[64]
#define MM_SA_H   0
#define MM_SA_L   25920
#define MM_SB     51840
#define MM_SBIAS  88704
#define MM_SMEM   88960

template<bool NORM>
__global__ __launch_bounds__(256, 2)
void conv_mma_kernel(const float* __restrict__ in, const __nv_bfloat16* __restrict__ wB,
                     const float* __restrict__ bias, float* __restrict__ out,
                     int C, int H, int W, int nstage)
{
    extern __shared__ char smem[];
    const uint32_t sb = smem_u32(smem);
    const int tid = threadIdx.x, wid = tid >> 5, lane = tid & 31;
    const int wm = wid & 3, wn = wid >> 2;
    const int bcol = blockIdx.x * 16, brow = blockIdx.y * 8, n = blockIdx.z;
    const size_t HW = (size_t)H * W;
    const int nSlabs = C >> 6, TT = nSlabs * 9;
    float* sBias = (float*)(smem + MM_SBIAS);
    if (tid < 64) sBias[tid] = bias[tid];

    // per-lane A (ldmatrix) base addrs: lanes 0-15 rows, 16-31 rows at +16B (k8-15)
    const int ml = lane & 15;
    const uint32_t koff = (lane >= 16) ? 16u : 0u;
    const uint32_t bp0 = (uint32_t)(((wm * 2 + 0) * 18 + ml) * 144) + koff;
    const uint32_t bp1 = (uint32_t)(((wm * 2 + 1) * 18 + ml) * 144) + koff;
    // per-lane B (lds) base: n = lane>>2, k0 = (lane&3)*2  -> conflict-free
    const uint32_t bBlane = (uint32_t)((wn * 32 + (lane >> 2)) * 144 + (lane & 3) * 4);

    float acc[2][4][4];
    #pragma unroll
    for (int mt = 0; mt < 2; mt++)
        #pragma unroll
        for (int nt = 0; nt < 4; nt++)
            #pragma unroll
            for (int k = 0; k < 4; k++) acc[mt][nt][k] = 0.0f;

    // initial B tile (tt=0) -> buf 0
    {
        const uint4* src = (const uint4*)wB;
        #pragma unroll
        for (int i = 0; i < 5; i++) {
            int j = tid + i * 256;
            if (j < 1152) *(uint4*)(smem + MM_SB + j * 16) = src[j];
        }
    }

    int buf = 0;
    for (int slab = 0; slab < nSlabs; slab++) {
        // ---- patch: 64 ch x 10x18, f32 -> bf16 hi/lo, BN folded, zero pad ----
        const float* inBase = in + (size_t)(n * C + slab * 64) * HW;
        for (int i = tid; i < 64 * 180; i += 256) {
            int c = i / 180, p = i % 180;
            int r = p / 18, cc = p % 18;
            int gr = brow - 1 + r, gc = bcol - 1 + cc;
            float v = 0.0f;
            if (gr >= 0 && gr < H && gc >= 0 && gc < W) {
                v = inBase[(size_t)c * HW + (size_t)gr * W + gc];
                if (NORM) v = fmaf(v, g_nsc[nstage][slab * 64 + c], g_nsh[nstage][slab * 64 + c]);
            }
            __nv_bfloat16 h = __float2bfloat16(v);
            __nv_bfloat16 l = __float2bfloat16(v - __bfloat162float(h));
            *(__nv_bfloat16*)(smem + MM_SA_H + p * 144 + c * 2) = h;
            *(__nv_bfloat16*)(smem + MM_SA_L + p * 144 + c * 2) = l;
        }
        __syncthreads();

        for (int tap = 0; tap < 9; tap++) {
            const int tt = slab * 9 + tap;
            // prefetch next B tile into registers (stored after mma)
            uint4 pf[5];
            const bool havePf = (tt + 1 < TT);
            if (havePf) {
                const uint4* src = (const uint4*)(wB + (size_t)(tt + 1) * 9216);
                #pragma unroll
                for (int i = 0; i < 5; i++) {
                    int j = tid + i * 256;
                    if (j < 1152) pf[i] = src[j];
                }
            }

            const int di = tap / 3, dj = tap % 3;
            const uint32_t toff = (uint32_t)((di * 18 + dj) * 144);
            const uint32_t aH0 = sb + MM_SA_H + bp0 + toff;
            const uint32_t aH1 = sb + MM_SA_H + bp1 + toff;
            const uint32_t bBase = sb + MM_SB + (uint32_t)buf * 18432 + bBlane;

            #pragma unroll
            for (int ks = 0; ks < 4; ks++) {
                uint32_t ah0[4], ah1[4], al0[4], al1[4];
                ldmatrix4(ah0, aH0 + ks * 32);
                ldmatrix4(ah1, aH1 + ks * 32);
                ldmatrix4(al0, aH0 + 25920 + ks * 32);
                ldmatrix4(al1, aH1 + 25920 + ks * 32);
                uint32_t bh[4][2], bl[4][2];
                #pragma unroll
                for (int nt = 0; nt < 4; nt++) {
                    uint32_t o = bBase + (uint32_t)(nt * 1152 + ks * 32) - sb;
                    const char* sp = smem + o;
                    bh[nt][0] = *(const uint32_t*)(sp);
                    bh[nt][1] = *(const uint32_t*)(sp + 16);
                    bl[nt][0] = *(const uint32_t*)(sp + 9216);
                    bl[nt][1] = *(const uint32_t*)(sp + 9216 + 16);
                }
                #pragma unroll
                for (int nt = 0; nt < 4; nt++) {
                    mma_bf16(acc[0][nt], ah0, bh[nt]);
                    mma_bf16(acc[1][nt], ah1, bh[nt]);
                    mma_bf16(acc[0][nt], ah0, bl[nt]);
                    mma_bf16(acc[1][nt], ah1, bl[nt]);
                    mma_bf16(acc[0][nt], al0, bh[nt]);
                    mma_bf16(acc[1][nt], al1, bh[nt]);
                }
            }

            if (havePf) {
                char* dst = smem + MM_SB + (buf ^ 1) * 18432;
                #pragma unroll
                for (int i = 0; i < 5; i++) {
                    int j = tid + i * 256;
                    if (j < 1152) *(uint4*)(dst + j * 16) = pf[i];
                }
            }
            __syncthreads();
            buf ^= 1;
        }
    }

    // ---- epilogue: stage C in smem (reuse patch area), coalesced store ----
    float* sC = (float*)smem;          // sC[oc*128 + m]
    const int l4 = lane >> 2, l2 = (lane & 3) * 2;
    #pragma unroll
    for (int mt = 0; mt < 2; mt++)
        #pragma unroll
        for (int nt = 0; nt < 4; nt++) {
            int row = wm * 32 + mt * 16 + l4;
            int col = wn * 32 + nt * 8 + l2;
            sC[col * 128 + row]           = acc[mt][nt][0];
            sC[(col + 1) * 128 + row]     = acc[mt][nt][1];
            sC[col * 128 + row + 8]       = acc[mt][nt][2];
            sC[(col + 1) * 128 + row + 8] = acc[mt][nt][3];
        }
    __syncthreads();
    for (int i = tid; i < 8192; i += 256) {
        int oc = i >> 7, m = i & 127;
        int pr = m >> 4, pc = m & 15;
        out[((size_t)(n * 64 + oc) * H + brow + pr) * W + bcol + pc] = sC[i] + sBias[oc];
    }
}

// ===================== elementwise / DWT kernels ===========================
__global__ void bnrelu_dwt_kernel(const float* __restrict__ x2,
                                  float* __restrict__ skip, float* __restrict__ dwt) {
    size_t i = (size_t)blockIdx.x * blockDim.x + threadIdx.x;
    if (i >= DWT_ELEMS) return;
    int x = (int)(i & 255), y = (int)((i >> 8) & 255);
    int c = (int)((i >> 16) & 63), n = (int)(i >> 22);
    const float sc = g_nsc[1][c], sh = g_nsh[1][c];
    const size_t base = ((size_t)(n * 64 + c) * 512 + 2 * y) * 512 + 2 * x;
    float2 r0 = *(const float2*)(x2 + base);
    float2 r1 = *(const float2*)(x2 + base + 512);
    float s00 = fmaxf(fmaf(r0.x, sc, sh), 0.0f);
    float s01 = fmaxf(fmaf(r0.y, sc, sh), 0.0f);
    float s10 = fmaxf(fmaf(r1.x, sc, sh), 0.0f);
    float s11 = fmaxf(fmaf(r1.y, sc, sh), 0.0f);
    *(float2*)(skip + base)       = make_float2(s00, s01);
    *(float2*)(skip + base + 512) = make_float2(s10, s11);
    size_t ob = ((size_t)(n * 256 + c)) * 65536 + (size_t)y * 256 + x;
    dwt[ob                 ] = 0.5f * (s00 + s01 + s10 + s11);
    dwt[ob +  64ull * 65536] = 0.5f * (s00 + s01 - s10 - s11);
    dwt[ob + 128ull * 65536] = 0.5f * (s00 - s01 + s10 - s11);
    dwt[ob + 192ull * 65536] = 0.5f * (s00 - s01 - s10 + s11);
}

__global__ void bnrelu4_kernel(float* __restrict__ buf) {
    size_t i4 = (size_t)blockIdx.x * blockDim.x + threadIdx.x;
    if (i4 >= (DWT_ELEMS >> 2)) return;
    int c = (int)((i4 >> 14) & 63);
    const float sc = g_nsc[2][c], sh = g_nsh[2][c];
    float4 v = ((float4*)buf)[i4];
    v.x = fmaxf(fmaf(v.x, sc, sh), 0.0f);
    v.y = fmaxf(fmaf(v.y, sc, sh), 0.0f);
    v.z = fmaxf(fmaf(v.z, sc, sh), 0.0f);
    v.w = fmaxf(fmaf(v.w, sc, sh), 0.0f);
    ((float4*)buf)[i4] = v;
}

// ================================ launch ===================================
extern "C" void kernel_launch(void* const* d_in, const int* in_sizes, int n_in,
                              void* d_out, int out_size) {
    const float* x   = (const float*)d_in[0];
    const float* w1  = (const float*)d_in[1];
    const float* b1  = (const float*)d_in[2];
    const float* g1  = (const float*)d_in[3];
    const float* be1 = (const float*)d_in[4];
    const float* w2  = (const float*)d_in[5];
    const float* b2  = (const float*)d_in[6];
    const float* g2  = (const float*)d_in[7];
    const float* be2 = (const float*)d_in[8];
    const float* w3  = (const float*)d_in[9];
    const float* b3  = (const float*)d_in[10];
    const float* g3  = (const float*)d_in[11];
    const float* be3 = (const float*)d_in[12];

    float* out      = (float*)d_out;
    float* dwt_out  = out;
    float* skip_con = out + DWT_ELEMS;

    float *bufA, *bufB, *wT;
    __nv_bfloat16* wB;
    cudaGetSymbolAddress((void**)&bufA, g_bufA);
    cudaGetSymbolAddress((void**)&bufB, g_bufB);
    cudaGetSymbolAddress((void**)&wT,   g_wT);
    cudaGetSymbolAddress((void**)&wB,   g_wB);

    cudaFuncSetAttribute(conv_mma_kernel<true>,
                         cudaFuncAttributeMaxDynamicSharedMemorySize, MM_SMEM);
    cudaFuncSetAttribute(conv_mma_kernel<false>,
                         cudaFuncAttributeMaxDynamicSharedMemorySize, MM_SMEM);

    const double inv_cnt_hi = 1.0 / (4.0 * 512.0 * 512.0);

    zero_stats_kernel<<<1, 192>>>();

    // conv1 (FFMA, C=3) -> bufA, stats stage 0
    transpose_w_kernel<<<(3 * 576 + 255) / 256, 256>>>(w1, wT, 3);
    conv3x3_kernel<false><<<dim3(16, 64, 4), 512>>>(x, wT, b1, bufA, 3, 512, 512, 0, 0);
    finalize_stats_kernel<<<1, 64>>>(0, g1, be1, inv_cnt_hi);

    // conv2 (mma.sync, BN1 folded): bufA -> bufB
    prep_wmma_kernel<<<(82944 + 255) / 256, 256>>>(w2, wB, 64);
    conv_mma_kernel<true><<<dim3(32, 64, 4), 256, MM_SMEM>>>(
        bufA, wB, b2, bufB, 64, 512, 512, 0);
    stats2_kernel<<<64, 1024>>>(bufB, 1, 512 * 512, g2, be2);

    // fused BN2+ReLU+DWT: bufB -> skip_con + bufA(dwt)
    bnrelu_dwt_kernel<<<65536, 256>>>(bufB, skip_con, bufA);

    // conv3 (mma.sync): bufA(dwt, C=256) -> dwt_out (raw)
    prep_wmma_kernel<<<(331776 + 255) / 256, 256>>>(w3, wB, 256);
    conv_mma_kernel<false><<<dim3(16, 32, 4), 256, MM_SMEM>>>(
        bufA, wB, b3, dwt_out, 256, 256, 256, 0);
    stats2_kernel<<<64, 1024>>>(dwt_out, 2, 256 * 256, g3, be3);

    // final BN3+ReLU in place
    bnrelu4_kernel<<<16384, 256>>>(dwt_out);
}